// round 1
// baseline (speedup 1.0000x reference)
#include <cuda_runtime.h>
#include <math.h>

#define NN 100000
#define EE 1600000
#define F_IN 1433
#define DD 64
#define HH 4
#define DHH 16
#define DEPTH 3
#define ALPHA 0.9f

// ---------------- scratch (static device globals; no runtime allocation) ----
__device__ float g_x0[NN * DD];
__device__ float g_x [NN * DD];
__device__ float g_h [NN * DD];   // LN output, later reused as agg
__device__ float g_q [NN * DD];
__device__ float g_k [NN * DD];
__device__ float g_v [NN * DD];
__device__ float g_o [NN * DD];
__device__ int   g_deg[NN];
__device__ int   g_off[NN + 1];
__device__ int   g_pos[NN];
__device__ int   g_csr[EE];       // src node ids grouped by dst

// ---------------- CSR construction ----------------
__global__ void zero_deg_kernel() {
    int i = blockIdx.x * blockDim.x + threadIdx.x;
    if (i < NN) g_deg[i] = 0;
}

__global__ void hist_kernel(const int* __restrict__ ei) {
    int e = blockIdx.x * blockDim.x + threadIdx.x;
    if (e < EE) atomicAdd(&g_deg[ei[EE + e]], 1);
}

// one block, 1024 threads: chunked exclusive scan over N=100000 degrees
__global__ void scan_kernel() {
    __shared__ int ssum[1024];
    const int t = threadIdx.x;
    const int CHUNK = (NN + 1023) / 1024;   // 98
    int beg = t * CHUNK;
    int end = beg + CHUNK; if (end > NN) end = NN;
    int s = 0;
    for (int i = beg; i < end; ++i) s += g_deg[i];
    ssum[t] = s;
    __syncthreads();
    // inclusive Hillis-Steele scan
    for (int d = 1; d < 1024; d <<= 1) {
        int v = (t >= d) ? ssum[t - d] : 0;
        __syncthreads();
        ssum[t] += v;
        __syncthreads();
    }
    int run = (t == 0) ? 0 : ssum[t - 1];
    for (int i = beg; i < end; ++i) {
        g_off[i] = run;
        g_pos[i] = run;
        run += g_deg[i];
    }
    if (t == 1023) g_off[NN] = ssum[1023];
}

__global__ void fill_kernel(const int* __restrict__ ei) {
    int e = blockIdx.x * blockDim.x + threadIdx.x;
    if (e < EE) {
        int d = ei[EE + e];
        int p = atomicAdd(&g_pos[d], 1);
        g_csr[p] = ei[e];   // src
    }
}

// ---------------- generic tiled SGEMM: C[M x 64] = A[M x K] @ B[K x 64] -----
// BM=128, BN=64, BK=16, TM=8, TN=8, 128 threads
__global__ __launch_bounds__(128)
void gemm_kernel(const float* __restrict__ A, const float* __restrict__ B,
                 float* __restrict__ C, float* __restrict__ C2,
                 const float* __restrict__ bias, int M, int K) {
    const int BM = 128, BN = 64, BK = 16, TM = 8, TN = 8;
    __shared__ float As[BK][BM + 4];
    __shared__ float Bs[BK][BN];
    const int tid = threadIdx.x;
    const int trow = (tid / (BN / TN)) * TM;   // (tid/8)*8
    const int tcol = (tid % (BN / TN)) * TN;   // (tid%8)*8
    const int rowBase = blockIdx.x * BM;

    float acc[TM][TN];
#pragma unroll
    for (int i = 0; i < TM; ++i)
#pragma unroll
        for (int j = 0; j < TN; ++j) acc[i][j] = 0.f;

    for (int k0 = 0; k0 < K; k0 += BK) {
        // A tile (BM x BK) -> transposed in smem
#pragma unroll 4
        for (int i = tid; i < BM * BK; i += 128) {
            int r = i / BK, kk = i % BK;
            int gr = rowBase + r, gk = k0 + kk;
            As[kk][r] = (gr < M && gk < K) ? A[(long)gr * K + gk] : 0.f;
        }
        // B tile (BK x 64)
#pragma unroll
        for (int i = tid; i < BK * BN; i += 128) {
            int kk = i / BN, c = i % BN;
            int gk = k0 + kk;
            Bs[kk][c] = (gk < K) ? B[gk * 64 + c] : 0.f;
        }
        __syncthreads();
#pragma unroll
        for (int kk = 0; kk < BK; ++kk) {
            float a[TM], b[TN];
#pragma unroll
            for (int i = 0; i < TM; ++i) a[i] = As[kk][trow + i];
#pragma unroll
            for (int j = 0; j < TN; ++j) b[j] = Bs[kk][tcol + j];
#pragma unroll
            for (int i = 0; i < TM; ++i)
#pragma unroll
                for (int j = 0; j < TN; ++j) acc[i][j] += a[i] * b[j];
        }
        __syncthreads();
    }
#pragma unroll
    for (int i = 0; i < TM; ++i) {
        int gr = rowBase + trow + i;
        if (gr < M) {
#pragma unroll
            for (int j = 0; j < TN; ++j) {
                float val = acc[i][j] + (bias ? bias[tcol + j] : 0.f);
                C[(long)gr * 64 + tcol + j] = val;
                if (C2) C2[(long)gr * 64 + tcol + j] = val;
            }
        }
    }
}

// ---------------- layer norm: warp per row ----------------
__global__ void ln_kernel(const float* __restrict__ scale,
                          const float* __restrict__ bias) {
    int warp = (blockIdx.x * blockDim.x + threadIdx.x) >> 5;
    int lane = threadIdx.x & 31;
    if (warp >= NN) return;
    const float* xr = g_x + (size_t)warp * 64;
    float x0v = xr[lane], x1v = xr[lane + 32];
    float s = x0v + x1v;
    float sq = x0v * x0v + x1v * x1v;
#pragma unroll
    for (int o = 16; o; o >>= 1) {
        s  += __shfl_xor_sync(~0u, s,  o);
        sq += __shfl_xor_sync(~0u, sq, o);
    }
    float mu = s * (1.f / 64.f);
    float var = sq * (1.f / 64.f) - mu * mu;
    float rstd = rsqrtf(var + 1e-5f);
    float* hr = g_h + (size_t)warp * 64;
    hr[lane]      = (x0v - mu) * rstd * scale[lane]      + bias[lane];
    hr[lane + 32] = (x1v - mu) * rstd * scale[lane + 32] + bias[lane + 32];
}

// ---------------- fused edge attention: warp per dst node, online softmax ---
// lane owns value slots (h=lane>>4, d=lane&15) and (h=2+(lane>>4), d=lane&15).
// per-head dot = shuffle reduction within 16-lane halves.
__global__ __launch_bounds__(256)
void attn_kernel() {
    int warp = (blockIdx.x * blockDim.x + threadIdx.x) >> 5;
    int lane = threadIdx.x & 31;
    if (warp >= NN) return;
    const float* qr = g_q + (size_t)warp * 64;
    float q0 = qr[lane], q1 = qr[lane + 32];
    float m0 = -1e30f, m1 = -1e30f, l0 = 0.f, l1 = 0.f, a0 = 0.f, a1 = 0.f;
    int beg = g_off[warp], end = g_off[warp + 1];
    for (int e = beg; e < end; ++e) {
        int s = g_csr[e];
        const float* kr = g_k + (size_t)s * 64;
        const float* vr = g_v + (size_t)s * 64;
        float d0 = q0 * kr[lane];
        float d1 = q1 * kr[lane + 32];
        float v0 = vr[lane];
        float v1 = vr[lane + 32];
#pragma unroll
        for (int o = 8; o; o >>= 1) {
            d0 += __shfl_xor_sync(~0u, d0, o);
            d1 += __shfl_xor_sync(~0u, d1, o);
        }
        d0 *= 0.25f; d1 *= 0.25f;   // DH^-0.5
        float nm0 = fmaxf(m0, d0), nm1 = fmaxf(m1, d1);
        float c0 = expf(m0 - nm0), c1 = expf(m1 - nm1);
        float p0 = expf(d0 - nm0), p1 = expf(d1 - nm1);
        l0 = l0 * c0 + p0;        l1 = l1 * c1 + p1;
        a0 = a0 * c0 + p0 * v0;   a1 = a1 * c1 + p1 * v1;
        m0 = nm0; m1 = nm1;
    }
    float* ag = g_h + (size_t)warp * 64;   // reuse h as agg
    ag[lane]      = a0 / (l0 + 1e-9f);
    ag[lane + 32] = a1 / (l1 + 1e-9f);
}

// ---------------- gated residual + alpha mix: warp per row ----------------
__global__ void gate_kernel(const float* __restrict__ gw,
                            const float* __restrict__ gbp,
                            float* __restrict__ dst) {
    int warp = (blockIdx.x * blockDim.x + threadIdx.x) >> 5;
    int lane = threadIdx.x & 31;
    if (warp >= NN) return;
    size_t base = (size_t)warp * 64;
    float o0 = g_o[base + lane],  o1 = g_o[base + lane + 32];
    float r0 = g_x[base + lane],  r1 = g_x[base + lane + 32];
    float z0 = g_x0[base + lane], z1 = g_x0[base + lane + 32];
    float s = o0 * gw[lane]        + o1 * gw[lane + 32]
            + r0 * gw[64 + lane]   + r1 * gw[96 + lane]
            + (o0 - r0) * gw[128 + lane] + (o1 - r1) * gw[160 + lane];
#pragma unroll
    for (int o = 16; o; o >>= 1) s += __shfl_xor_sync(~0u, s, o);
    float g = 1.f / (1.f + expf(-(s + gbp[0])));
    float mix0 = g * o0 + (1.f - g) * r0;
    float mix1 = g * o1 + (1.f - g) * r1;
    dst[base + lane]      = ALPHA * mix0 + (1.f - ALPHA) * z0;
    dst[base + lane + 32] = ALPHA * mix1 + (1.f - ALPHA) * z1;
}

// ---------------- launch ----------------
extern "C" void kernel_launch(void* const* d_in, const int* in_sizes, int n_in,
                              void* d_out, int out_size) {
    const float* nodes = (const float*)d_in[0];
    const int*   ei    = (const int*)  d_in[1];
    const float* emb_W = (const float*)d_in[2];
    const float* emb_b = (const float*)d_in[3];
    const float* ln_s  = (const float*)d_in[4];
    const float* ln_b  = (const float*)d_in[5];
    const float* Wq    = (const float*)d_in[6];
    const float* Wk    = (const float*)d_in[7];
    const float* Wv    = (const float*)d_in[8];
    const float* Wo    = (const float*)d_in[9];
    const float* gW    = (const float*)d_in[10];
    const float* gb    = (const float*)d_in[11];
    float* out = (float*)d_out;

    float *px0, *px, *ph, *pq, *pk, *pv, *po;
    cudaGetSymbolAddress((void**)&px0, g_x0);
    cudaGetSymbolAddress((void**)&px,  g_x);
    cudaGetSymbolAddress((void**)&ph,  g_h);
    cudaGetSymbolAddress((void**)&pq,  g_q);
    cudaGetSymbolAddress((void**)&pk,  g_k);
    cudaGetSymbolAddress((void**)&pv,  g_v);
    cudaGetSymbolAddress((void**)&po,  g_o);

    // CSR build (reused across all 3 layers)
    zero_deg_kernel<<<(NN + 255) / 256, 256>>>();
    hist_kernel<<<(EE + 255) / 256, 256>>>(ei);
    scan_kernel<<<1, 1024>>>();
    fill_kernel<<<(EE + 255) / 256, 256>>>(ei);

    // embedding GEMM: x0 = nodes @ emb_W + emb_b ; x = x0
    gemm_kernel<<<(NN + 127) / 128, 128>>>(nodes, emb_W, px0, px, emb_b,
                                           NN, F_IN);

    const int warpGrid = (NN + 7) / 8;   // 8 warps per 256-thread block
    for (int l = 0; l < DEPTH; ++l) {
        ln_kernel<<<warpGrid, 256>>>(ln_s + l * 64, ln_b + l * 64);
        gemm_kernel<<<(NN + 127) / 128, 128>>>(ph, Wq + l * 4096, pq,
                                               nullptr, nullptr, NN, 64);
        gemm_kernel<<<(NN + 127) / 128, 128>>>(ph, Wk + l * 4096, pk,
                                               nullptr, nullptr, NN, 64);
        gemm_kernel<<<(NN + 127) / 128, 128>>>(ph, Wv + l * 4096, pv,
                                               nullptr, nullptr, NN, 64);
        attn_kernel<<<warpGrid, 256>>>();                 // agg -> g_h
        gemm_kernel<<<(NN + 127) / 128, 128>>>(ph, Wo + l * 4096, po,
                                               nullptr, nullptr, NN, 64);
        float* dst = (l == DEPTH - 1) ? out : px;
        gate_kernel<<<warpGrid, 256>>>(gW + l * 192, gb + l, dst);
    }
}

// round 2
// speedup vs baseline: 1.8166x; 1.8166x over previous
#include <cuda_runtime.h>
#include <cuda_bf16.h>
#include <math.h>

#define NN 100000
#define EE 1600000
#define F_IN 1433
#define DD 64
#define DEPTH 3
#define ALPHA 0.9f
#define KC_EMB 90   // ceil(1433/16)

// ---------------- scratch (static device globals) ----------------
__device__ float g_x0[NN * DD];
__device__ float g_x [NN * DD];
__device__ float g_h [NN * DD];   // LN output, later reused as agg
__device__ float g_q [NN * DD];
__device__ float g_k [NN * DD];
__device__ float g_v [NN * DD];
__device__ float g_o [NN * DD];
__device__ int   g_deg[NN];
__device__ int   g_off[NN + 1];
__device__ int   g_pos[NN];
__device__ int   g_csr[EE];
// packed split-bf16 B fragments: per (kc, ntile, lane) -> uint4 {b0hi,b1hi,b0lo,b1lo}
__device__ uint4 g_Bemb[KC_EMB * 256];       // 1433x64 embedding weight
__device__ uint4 g_Bw[12 * 1024];            // 12 matrices (q,k,v,o x 3 layers), K=64 -> KC=4

// ---------------- helpers ----------------
__device__ __forceinline__ void split2(float x, float y, unsigned& hi, unsigned& lo) {
    __nv_bfloat162 h = __floats2bfloat162_rn(x, y);
    float rx = x - __low2float(h);
    float ry = y - __high2float(h);
    __nv_bfloat162 l = __floats2bfloat162_rn(rx, ry);
    hi = *reinterpret_cast<unsigned*>(&h);
    lo = *reinterpret_cast<unsigned*>(&l);
}

__device__ __forceinline__ void mma16816(float* c, const unsigned* a,
                                         unsigned b0, unsigned b1) {
    asm volatile(
        "mma.sync.aligned.m16n8k16.row.col.f32.bf16.bf16.f32 "
        "{%0,%1,%2,%3},{%4,%5,%6,%7},{%8,%9},{%0,%1,%2,%3};\n"
        : "+f"(c[0]), "+f"(c[1]), "+f"(c[2]), "+f"(c[3])
        : "r"(a[0]), "r"(a[1]), "r"(a[2]), "r"(a[3]), "r"(b0), "r"(b1));
}

// ---------------- B packing ----------------
__global__ void pack_b_kernel(const float* __restrict__ B, uint4* __restrict__ out,
                              int K, int KC) {
    int idx = blockIdx.x * blockDim.x + threadIdx.x;
    if (idx >= KC * 256) return;
    int lane = idx & 31, nt = (idx >> 5) & 7, kc = idx >> 8;
    int col = nt * 8 + (lane >> 2);
    int kr = kc * 16 + (lane & 3) * 2;
    float f0 = (kr     < K) ? B[(kr    ) * 64 + col] : 0.f;
    float f1 = (kr + 1 < K) ? B[(kr + 1) * 64 + col] : 0.f;
    float f2 = (kr + 8 < K) ? B[(kr + 8) * 64 + col] : 0.f;
    float f3 = (kr + 9 < K) ? B[(kr + 9) * 64 + col] : 0.f;
    unsigned h0, l0, h1, l1;
    split2(f0, f1, h0, l0);
    split2(f2, f3, h1, l1);
    out[idx] = make_uint4(h0, h1, l0, l1);
}

__global__ void pack_w_kernel(const float* __restrict__ Wq, const float* __restrict__ Wk,
                              const float* __restrict__ Wv, const float* __restrict__ Wo,
                              uint4* __restrict__ out) {
    int idx = blockIdx.x * blockDim.x + threadIdx.x;
    if (idx >= 12 * 1024) return;
    int m = idx >> 10;
    int l = m >> 2, w = m & 3;
    const float* B = (w == 0 ? Wq : w == 1 ? Wk : w == 2 ? Wv : Wo) + l * 4096;
    int rest = idx & 1023;
    int lane = rest & 31, nt = (rest >> 5) & 7, kc = rest >> 8;
    int col = nt * 8 + (lane >> 2);
    int kr = kc * 16 + (lane & 3) * 2;
    float f0 = B[(kr    ) * 64 + col];
    float f1 = B[(kr + 1) * 64 + col];
    float f2 = B[(kr + 8) * 64 + col];
    float f3 = B[(kr + 9) * 64 + col];
    unsigned h0, l0, h1, l1;
    split2(f0, f1, h0, l0);
    split2(f2, f3, h1, l1);
    out[idx] = make_uint4(h0, h1, l0, l1);
}

// ---------------- split-bf16 tensor-core GEMM ----------------
// C[m][M x 64] = A[M x K] @ B_m[K x 64]   for m in 0..NB-1
// block = 128 thr (4 warps); warp owns 16 rows x 64 cols of output.
__device__ __forceinline__ float ldA(const float* __restrict__ A, long off, int c,
                                     int K, bool rok) {
    return (rok && c < K) ? __ldg(A + off + c) : 0.f;
}

template <int NB>
__global__ __launch_bounds__(128)
void mma_gemm_kernel(const float* __restrict__ A, const uint4* __restrict__ Bp,
                     float* __restrict__ O0, float* __restrict__ O1,
                     float* __restrict__ O2, float* __restrict__ Odup,
                     const float* __restrict__ bias, int M, int K, int KC) {
    const int warp = threadIdx.x >> 5, lane = threadIdx.x & 31;
    const int r0 = blockIdx.x * 64 + warp * 16 + (lane >> 2);
    const bool rok0 = r0 < M, rok1 = (r0 + 8) < M;
    const long off0 = (long)r0 * K, off1 = (long)(r0 + 8) * K;

    float acc[NB][8][4];
#pragma unroll
    for (int m = 0; m < NB; ++m)
#pragma unroll
        for (int nt = 0; nt < 8; ++nt)
#pragma unroll
            for (int j = 0; j < 4; ++j) acc[m][nt][j] = 0.f;

    for (int kc = 0; kc < KC; ++kc) {
        int c0 = kc * 16 + (lane & 3) * 2;
        float f0 = ldA(A, off0, c0,     K, rok0);
        float f1 = ldA(A, off0, c0 + 1, K, rok0);
        float f2 = ldA(A, off1, c0,     K, rok1);
        float f3 = ldA(A, off1, c0 + 1, K, rok1);
        float f4 = ldA(A, off0, c0 + 8, K, rok0);
        float f5 = ldA(A, off0, c0 + 9, K, rok0);
        float f6 = ldA(A, off1, c0 + 8, K, rok1);
        float f7 = ldA(A, off1, c0 + 9, K, rok1);
        unsigned ahi[4], alo[4];
        split2(f0, f1, ahi[0], alo[0]);
        split2(f2, f3, ahi[1], alo[1]);
        split2(f4, f5, ahi[2], alo[2]);
        split2(f6, f7, ahi[3], alo[3]);

        const uint4* bp = Bp + (size_t)kc * 256 + lane;
#pragma unroll
        for (int m = 0; m < NB; ++m) {
            const uint4* bm = bp + (size_t)m * KC * 256;
#pragma unroll
            for (int nt = 0; nt < 8; ++nt) {
                uint4 b = __ldg(&bm[nt * 32]);
                mma16816(acc[m][nt], ahi, b.x, b.y);  // hi*hi
                mma16816(acc[m][nt], alo, b.x, b.y);  // lo*hi
                mma16816(acc[m][nt], ahi, b.z, b.w);  // hi*lo
            }
        }
    }

    float* outs[3];
    outs[0] = O0; outs[1] = O1; outs[2] = O2;
#pragma unroll
    for (int m = 0; m < NB; ++m) {
        float* O = outs[m];
#pragma unroll
        for (int nt = 0; nt < 8; ++nt) {
            int cc = nt * 8 + (lane & 3) * 2;
            float b0 = bias ? bias[cc] : 0.f;
            float b1 = bias ? bias[cc + 1] : 0.f;
            if (rok0) {
                float2 v = make_float2(acc[m][nt][0] + b0, acc[m][nt][1] + b1);
                *(float2*)(O + (long)r0 * 64 + cc) = v;
                if (Odup) *(float2*)(Odup + (long)r0 * 64 + cc) = v;
            }
            if (rok1) {
                float2 v = make_float2(acc[m][nt][2] + b0, acc[m][nt][3] + b1);
                *(float2*)(O + (long)(r0 + 8) * 64 + cc) = v;
                if (Odup) *(float2*)(Odup + (long)(r0 + 8) * 64 + cc) = v;
            }
        }
    }
}

// ---------------- CSR construction ----------------
__global__ void zero_deg_kernel() {
    int i = blockIdx.x * blockDim.x + threadIdx.x;
    if (i < NN) g_deg[i] = 0;
}

__global__ void hist_kernel(const int* __restrict__ ei) {
    int e = blockIdx.x * blockDim.x + threadIdx.x;
    if (e < EE) atomicAdd(&g_deg[ei[EE + e]], 1);
}

__global__ void scan_kernel() {
    __shared__ int ssum[1024];
    const int t = threadIdx.x;
    const int CHUNK = (NN + 1023) / 1024;
    int beg = t * CHUNK;
    int end = beg + CHUNK; if (end > NN) end = NN;
    int s = 0;
    for (int i = beg; i < end; ++i) s += g_deg[i];
    ssum[t] = s;
    __syncthreads();
    for (int d = 1; d < 1024; d <<= 1) {
        int v = (t >= d) ? ssum[t - d] : 0;
        __syncthreads();
        ssum[t] += v;
        __syncthreads();
    }
    int run = (t == 0) ? 0 : ssum[t - 1];
    for (int i = beg; i < end; ++i) {
        g_off[i] = run;
        g_pos[i] = run;
        run += g_deg[i];
    }
    if (t == 1023) g_off[NN] = ssum[1023];
}

__global__ void fill_kernel(const int* __restrict__ ei) {
    int e = blockIdx.x * blockDim.x + threadIdx.x;
    if (e < EE) {
        int d = ei[EE + e];
        int p = atomicAdd(&g_pos[d], 1);
        g_csr[p] = ei[e];
    }
}

// ---------------- layer norm: warp per row ----------------
__global__ void ln_kernel(const float* __restrict__ scale,
                          const float* __restrict__ bias) {
    int warp = (blockIdx.x * blockDim.x + threadIdx.x) >> 5;
    int lane = threadIdx.x & 31;
    if (warp >= NN) return;
    const float* xr = g_x + (size_t)warp * 64;
    float x0v = xr[lane], x1v = xr[lane + 32];
    float s = x0v + x1v;
    float sq = x0v * x0v + x1v * x1v;
#pragma unroll
    for (int o = 16; o; o >>= 1) {
        s  += __shfl_xor_sync(~0u, s,  o);
        sq += __shfl_xor_sync(~0u, sq, o);
    }
    float mu = s * (1.f / 64.f);
    float var = sq * (1.f / 64.f) - mu * mu;
    float rstd = rsqrtf(var + 1e-5f);
    float* hr = g_h + (size_t)warp * 64;
    hr[lane]      = (x0v - mu) * rstd * scale[lane]      + bias[lane];
    hr[lane + 32] = (x1v - mu) * rstd * scale[lane + 32] + bias[lane + 32];
}

// ---------------- fused edge attention: warp per dst node, online softmax ---
__global__ __launch_bounds__(256)
void attn_kernel() {
    int warp = (blockIdx.x * blockDim.x + threadIdx.x) >> 5;
    int lane = threadIdx.x & 31;
    if (warp >= NN) return;
    const float* qr = g_q + (size_t)warp * 64;
    float q0 = qr[lane], q1 = qr[lane + 32];
    float m0 = -1e30f, m1 = -1e30f, l0 = 0.f, l1 = 0.f, a0 = 0.f, a1 = 0.f;
    int beg = g_off[warp], end = g_off[warp + 1];
    for (int e = beg; e < end; ++e) {
        int s = g_csr[e];
        const float* kr = g_k + (size_t)s * 64;
        const float* vr = g_v + (size_t)s * 64;
        float d0 = q0 * kr[lane];
        float d1 = q1 * kr[lane + 32];
        float v0 = vr[lane];
        float v1 = vr[lane + 32];
#pragma unroll
        for (int o = 8; o; o >>= 1) {
            d0 += __shfl_xor_sync(~0u, d0, o);
            d1 += __shfl_xor_sync(~0u, d1, o);
        }
        d0 *= 0.25f; d1 *= 0.25f;
        float nm0 = fmaxf(m0, d0), nm1 = fmaxf(m1, d1);
        float c0 = expf(m0 - nm0), c1 = expf(m1 - nm1);
        float p0 = expf(d0 - nm0), p1 = expf(d1 - nm1);
        l0 = l0 * c0 + p0;        l1 = l1 * c1 + p1;
        a0 = a0 * c0 + p0 * v0;   a1 = a1 * c1 + p1 * v1;
        m0 = nm0; m1 = nm1;
    }
    float* ag = g_h + (size_t)warp * 64;
    ag[lane]      = a0 / (l0 + 1e-9f);
    ag[lane + 32] = a1 / (l1 + 1e-9f);
}

// ---------------- gated residual + alpha mix ----------------
__global__ void gate_kernel(const float* __restrict__ gw,
                            const float* __restrict__ gbp,
                            float* __restrict__ dst) {
    int warp = (blockIdx.x * blockDim.x + threadIdx.x) >> 5;
    int lane = threadIdx.x & 31;
    if (warp >= NN) return;
    size_t base = (size_t)warp * 64;
    float o0 = g_o[base + lane],  o1 = g_o[base + lane + 32];
    float r0 = g_x[base + lane],  r1 = g_x[base + lane + 32];
    float z0 = g_x0[base + lane], z1 = g_x0[base + lane + 32];
    float s = o0 * gw[lane]        + o1 * gw[lane + 32]
            + r0 * gw[64 + lane]   + r1 * gw[96 + lane]
            + (o0 - r0) * gw[128 + lane] + (o1 - r1) * gw[160 + lane];
#pragma unroll
    for (int o = 16; o; o >>= 1) s += __shfl_xor_sync(~0u, s, o);
    float g = 1.f / (1.f + expf(-(s + gbp[0])));
    float mix0 = g * o0 + (1.f - g) * r0;
    float mix1 = g * o1 + (1.f - g) * r1;
    dst[base + lane]      = ALPHA * mix0 + (1.f - ALPHA) * z0;
    dst[base + lane + 32] = ALPHA * mix1 + (1.f - ALPHA) * z1;
}

// ---------------- launch ----------------
extern "C" void kernel_launch(void* const* d_in, const int* in_sizes, int n_in,
                              void* d_out, int out_size) {
    const float* nodes = (const float*)d_in[0];
    const int*   ei    = (const int*)  d_in[1];
    const float* emb_W = (const float*)d_in[2];
    const float* emb_b = (const float*)d_in[3];
    const float* ln_s  = (const float*)d_in[4];
    const float* ln_b  = (const float*)d_in[5];
    const float* Wq    = (const float*)d_in[6];
    const float* Wk    = (const float*)d_in[7];
    const float* Wv    = (const float*)d_in[8];
    const float* Wo    = (const float*)d_in[9];
    const float* gW    = (const float*)d_in[10];
    const float* gb    = (const float*)d_in[11];
    float* out = (float*)d_out;

    float *px0, *px, *ph, *pq, *pk, *pv, *po;
    uint4 *pBemb, *pBw;
    cudaGetSymbolAddress((void**)&px0, g_x0);
    cudaGetSymbolAddress((void**)&px,  g_x);
    cudaGetSymbolAddress((void**)&ph,  g_h);
    cudaGetSymbolAddress((void**)&pq,  g_q);
    cudaGetSymbolAddress((void**)&pk,  g_k);
    cudaGetSymbolAddress((void**)&pv,  g_v);
    cudaGetSymbolAddress((void**)&po,  g_o);
    cudaGetSymbolAddress((void**)&pBemb, g_Bemb);
    cudaGetSymbolAddress((void**)&pBw,   g_Bw);

    // weight packing (split-bf16 fragment layout)
    pack_b_kernel<<<(KC_EMB * 256 + 255) / 256, 256>>>(emb_W, pBemb, F_IN, KC_EMB);
    pack_w_kernel<<<(12 * 1024 + 255) / 256, 256>>>(Wq, Wk, Wv, Wo, pBw);

    // CSR build (reused across layers)
    zero_deg_kernel<<<(NN + 255) / 256, 256>>>();
    hist_kernel<<<(EE + 255) / 256, 256>>>(ei);
    scan_kernel<<<1, 1024>>>();
    fill_kernel<<<(EE + 255) / 256, 256>>>(ei);

    const int gemmGrid = (NN + 63) / 64;   // 1563
    // embedding: x0 = nodes @ emb_W + emb_b ; x = x0
    mma_gemm_kernel<1><<<gemmGrid, 128>>>(nodes, pBemb, px0, nullptr, nullptr,
                                          px, emb_b, NN, F_IN, KC_EMB);

    const int warpGrid = (NN + 7) / 8;
    for (int l = 0; l < DEPTH; ++l) {
        ln_kernel<<<warpGrid, 256>>>(ln_s + l * 64, ln_b + l * 64);
        // fused q,k,v = h @ {Wq,Wk,Wv}
        mma_gemm_kernel<3><<<gemmGrid, 128>>>(ph, pBw + (size_t)(l * 4) * 1024,
                                              pq, pk, pv, nullptr, nullptr,
                                              NN, 64, 4);
        attn_kernel<<<warpGrid, 256>>>();   // agg -> g_h
        mma_gemm_kernel<1><<<gemmGrid, 128>>>(ph, pBw + (size_t)(l * 4 + 3) * 1024,
                                              po, nullptr, nullptr, nullptr,
                                              nullptr, NN, 64, 4);
        float* dst = (l == DEPTH - 1) ? out : px;
        gate_kernel<<<warpGrid, 256>>>(gW + l * 192, gb + l, dst);
    }
}